// round 17
// baseline (speedup 1.0000x reference)
#include <cuda_runtime.h>

// SIRD batched integrator, sm_103a — round 16: RK4 @ dt=2 + quintic-Hermite
// dense output; leaner producer (single STS.64/step, BS=64).
// 64 blocks x 96 threads: warp 0 integrates (1 scenario/lane, 1024 RK4 steps
// of dt=2), warps 1-2 reconstruct odd points + write output.
//
// Round-15: producer measured 61 cyc/step vs 32-cycle chain — overhead was
// duplicate float4 STS (each state stored twice), reg copies, barrier every
// 32 steps. Now: store each state ONCE as float2 (STS.64) + one boundary
// entry per batch; consumers read entries i and i+1. BS=64 halves barrier
// amortization. Predicted ~48 cyc/step -> ~26us.
//
// Math unchanged: RK4 dt=2 in scaled vars (x,y)=(b*I,b*S); odd points via
// two-point quintic Hermite midpoint (vals + 1st/2nd derivs, tau=1):
//   m = (v0+v1)/2 + (5/16)(d0-d1) + (1/16)(s0+s1)
// D from RK-preserved invariant D=(mu/g)(N-S-I).

#define T_PTS  2048
#define NSTEP  1024                 // RK4 steps (dt=2)
#define BS     64                   // steps per batch
#define NB     (NSTEP / BS)         // 16 batches

__global__ void __launch_bounds__(96, 1)
sird_kernel(const float* __restrict__ alpha, float2* __restrict__ out) {
    __shared__ float2 buf[2][BS + 1][32];   // [slot][entry][lane] = (x,y) at t=2*entry

    const int lane = threadIdx.x & 31;
    const int wid  = threadIdx.x >> 5;
    const int scen = blockIdx.x * 32 + lane;

    const float beta  = alpha[scen * 3 + 0];
    const float gamma = alpha[scen * 3 + 1];
    const float mu    = alpha[scen * 3 + 2];

    float b = fmaxf(beta * 1.0e-7f, 1.0e-20f);   // beta/N (scale-invariant guard)
    const float g = gamma + mu;

    // ---- producer constants (dt = 2) ----
    const float mg   = -g;
    const float m2g  = -2.0f * g;
    const float cA2  = 1.0f - g;
    constexpr float h6 = 1.0f / 3.0f;            // dt/6
    const float mh6g = h6 * mg;                  // -g/3
    float x = b;                                 // b * I0
    float y = b * (1.0e7f - 1.0f);               // b * S0

    // ---- consumer constants ----
    const float inv_b = 1.0f / b;
    const float cD    = (mu / fmaxf(g, 1.0e-30f)) * inv_b;
    const float bN    = b * 1.0e7f;
    float4* __restrict__ o4 =
        reinterpret_cast<float4*>(out + (size_t)scen * T_PTS);

#define SUBSTEP2() do {                                           \
        float f1   = y * x;                                       \
        float cAx  = cA2 * x;                                     \
        float x2   = fmaf( 1.0f, f1, cAx);                        \
        float y2   = fmaf(-1.0f, f1, y);                          \
        float f2   = y2 * x2;                                     \
        float in3  = fmaf(mg, x2, x);                             \
        float pxw  = fmaf(2.0f, x2, x);                           \
        float x3   = fmaf( 1.0f, f2, in3);                        \
        float y3   = fmaf(-1.0f, f2, y);                          \
        float pf   = fmaf(2.0f, f2, f1);                          \
        float f3   = y3 * x3;                                     \
        float in4  = fmaf(m2g, x3, x);                            \
        float pxw2 = fmaf(2.0f, x3, pxw);                         \
        float x4   = fmaf( 2.0f, f3, in4);                        \
        float y4   = fmaf(-2.0f, f3, y);                          \
        float pf3  = fmaf(2.0f, f3, pf);                          \
        float W    = fmaf(mh6g, pxw2, x);                         \
        float base = fmaf(h6, pf3, W);                            \
        float C    = fmaf(-h6, pf3, y);                           \
        float v    = fmaf(h6, y4, mh6g);                          \
        float f4   = y4 * x4;                                     \
        x = fmaf(x4, v, base);                                    \
        y = fmaf(-h6, f4, C);                                     \
    } while (0)

    for (int k = 0; k <= NB; ++k) {
        if (wid == 0) {
            if (k < NB) {
                float2* bp = &buf[k & 1][0][lane];
                #pragma unroll 16
                for (int i = 0; i < BS; ++i) {
                    bp[i * 32] = make_float2(x, y);   // state at t = (k*BS+i)*2
                    SUBSTEP2();
                }
                bp[BS * 32] = make_float2(x, y);      // batch-right boundary
            }
        } else if (k > 0) {
            const int kb   = k - 1;
            const int slot = kb & 1;
            const int half = (wid - 1) * (BS / 2);     // 0 or 32
            const float2* bp = &buf[slot][half][lane];
            float4* dst = o4 + kb * BS + half;
            #pragma unroll 8
            for (int ii = 0; ii < BS / 2; ++ii) {
                float2 s0 = bp[ii * 32];
                float2 s1 = bp[(ii + 1) * 32];
                float x0 = s0.x, y0 = s0.y, x1 = s1.x, y1 = s1.y;
                // first/second derivatives at both endpoints
                float f0  = x0 * y0;
                float f1v = x1 * y1;
                float xp0 = fmaf(mg, x0, f0);
                float xp1 = fmaf(mg, x1, f1v);
                float t0  = y0 - g;
                float t1  = y1 - g;
                float xf0 = x0 * f0;
                float xf1 = x1 * f1v;
                float xpp0 = fmaf(xp0, t0, -xf0);
                float xpp1 = fmaf(xp1, t1, -xf1);
                float ypp0 = fmaf(-xp0, y0, xf0);
                float ypp1 = fmaf(-xp1, y1, xf1);
                // quintic Hermite midpoint (tau = 1)
                float mx = fmaf(0.0625f, xpp0 + xpp1,
                            fmaf(0.3125f, xp0 - xp1, 0.5f * (x0 + x1)));
                float my = fmaf(0.0625f, ypp0 + ypp1,
                            fmaf(0.3125f, f1v - f0, 0.5f * (y0 + y1)));
                // outputs: even point = left endpoint, odd = midpoint
                float Ie = x0 * inv_b;
                float De = cD * ((bN - x0) - y0);
                float Io = mx * inv_b;
                float Do = cD * ((bN - mx) - my);
                if (kb == 0 && half == 0 && ii == 0) { Ie = 1.0f; De = 0.0f; }
                dst[ii] = make_float4(Ie, De, Io, Do);
            }
        }
        __syncthreads();
    }
#undef SUBSTEP2
}

extern "C" void kernel_launch(void* const* d_in, const int* in_sizes, int n_in,
                              void* d_out, int out_size) {
    const float* alpha = (const float*)d_in[0];
    float2* out = (float2*)d_out;
    sird_kernel<<<T_PTS / 32, 96>>>(alpha, out);
}